// round 13
// baseline (speedup 1.0000x reference)
#include <cuda_runtime.h>
#include <cuda_bf16.h>
#include <mma.h>
#include <math.h>
#include <stdint.h>

using namespace nvcuda;

#define N_NODES 50000
#define N_EDGES 600000
#define N_GRAPHS 500
#define HID 128
#define N_LAYERS 3
#define N_CLASSES 10
#define N_TILES ((N_NODES + 127) / 128)   // 391

#define SCAN_B 512
#define SCAN_NB ((N_NODES + SCAN_B - 1) / SCAN_B)   // 98

#define LDA 136                       // bf16 stride (pad 8 halves = 16B)
#define LDC 132                       // fp32 epilogue stride
#define TILE_ELEMS (128 * LDA)        // 17408 bf16 per plane
#define SM_AH 0
#define SM_AL TILE_ELEMS
#define SM_BH (2 * TILE_ELEMS)
#define GEMM_SMEM (3 * TILE_ELEMS * 2)   // 104448 B -> 2 CTAs/SM

// ---------------- scratch (device globals; no allocs allowed) ----------------
__device__ int   g_cnt[N_NODES];
__device__ int   g_row[N_NODES + 1];
__device__ int   g_tmp[N_NODES];
__device__ int   g_csr[N_EDGES];
__device__ int   g_bsum[SCAN_NB];
__device__ int   g_boff[SCAN_NB];
__device__ float g_h0[(size_t)N_NODES * HID];
__device__ float g_h1[(size_t)N_NODES * HID];
__device__ float g_pool[N_GRAPHS * HID];
// mean in bf16 hi/lo, per-GEMM-tile padded-LDA layout: [tile][hi;lo][128*LDA]
__device__ __align__(16) __nv_bfloat16 g_Ablob[(size_t)N_TILES * 2 * TILE_ELEMS];
// W hi/lo blobs in padded-LDA layout: [layer][side][BH ; BL] bf16
__device__ __align__(16) __nv_bfloat16 g_Wblob[(size_t)N_LAYERS * 2 * 2 * TILE_ELEMS];

// ---------------- tiny utility kernels ----------------
__global__ void count_kernel(const int* __restrict__ dst, int* __restrict__ cnt, int nE) {
    int i = blockIdx.x * blockDim.x + threadIdx.x;
    if (i < nE) atomicAdd(&cnt[dst[i]], 1);
}

__global__ void scan_partial_kernel(const int* __restrict__ cnt, int* __restrict__ bsum) {
    __shared__ int sh[SCAN_B];
    int t = threadIdx.x;
    int i = blockIdx.x * SCAN_B + t;
    sh[t] = (i < N_NODES) ? cnt[i] : 0;
    __syncthreads();
#pragma unroll
    for (int off = SCAN_B / 2; off > 0; off >>= 1) {
        if (t < off) sh[t] += sh[t + off];
        __syncthreads();
    }
    if (t == 0) bsum[blockIdx.x] = sh[0];
}

__global__ void scan_bsum_kernel(const int* __restrict__ bsum, int* __restrict__ boff) {
    __shared__ int sh[128];
    int t = threadIdx.x;
    int v = (t < SCAN_NB) ? bsum[t] : 0;
    sh[t] = v;
    __syncthreads();
#pragma unroll
    for (int off = 1; off < 128; off <<= 1) {
        int add = (t >= off) ? sh[t - off] : 0;
        __syncthreads();
        sh[t] += add;
        __syncthreads();
    }
    if (t < SCAN_NB) boff[t] = sh[t] - v;
}

__global__ void scan_apply_kernel(const int* __restrict__ cnt, const int* __restrict__ boff,
                                  int* __restrict__ row, int* __restrict__ tmp) {
    __shared__ int sh[SCAN_B];
    int t = threadIdx.x;
    int i = blockIdx.x * SCAN_B + t;
    int v = (i < N_NODES) ? cnt[i] : 0;
    sh[t] = v;
    __syncthreads();
#pragma unroll
    for (int off = 1; off < SCAN_B; off <<= 1) {
        int add = (t >= off) ? sh[t - off] : 0;
        __syncthreads();
        sh[t] += add;
        __syncthreads();
    }
    int excl = boff[blockIdx.x] + sh[t] - v;
    if (i < N_NODES) { row[i] = excl; tmp[i] = excl; }
    if (i == N_NODES - 1) row[N_NODES] = excl + v;
}

__global__ void fill_csr_kernel(const int* __restrict__ src, const int* __restrict__ dst,
                                int* __restrict__ tmp, int* __restrict__ csr, int nE) {
    int i = blockIdx.x * blockDim.x + threadIdx.x;
    if (i < nE) {
        int p = atomicAdd(&tmp[dst[i]], 1);
        csr[p] = src[i];
    }
}

// ---------------- W prep: fp32 [j][k] -> bf16 hi/lo in padded-LDA layout -----
__global__ void prep_w_kernel(const float* __restrict__ Wl, const float* __restrict__ Wr,
                              __nv_bfloat16* __restrict__ blob) {
    int i = blockIdx.x * blockDim.x + threadIdx.x;   // one float4 per thread
    if (i >= N_LAYERS * 2 * 128 * 32) return;
    int kq   = i & 31;           // k/4
    int j    = (i >> 5) & 127;
    int side = (i >> 12) & 1;
    int l    = i >> 13;
    int k = kq << 2;
    const float* W = side ? Wr : Wl;
    float4 v = *(const float4*)(W + (size_t)l * 16384 + j * HID + k);
    __nv_bfloat162 h0 = __floats2bfloat162_rn(v.x, v.y);
    __nv_bfloat162 h1 = __floats2bfloat162_rn(v.z, v.w);
    float2 f0 = __bfloat1622float2(h0);
    float2 f1 = __bfloat1622float2(h1);
    __nv_bfloat162 l0 = __floats2bfloat162_rn(v.x - f0.x, v.y - f0.y);
    __nv_bfloat162 l1 = __floats2bfloat162_rn(v.z - f1.x, v.w - f1.y);
    __nv_bfloat16* base = blob + ((size_t)(l * 2 + side)) * 2 * TILE_ELEMS;
    *(__nv_bfloat162*)&base[j * LDA + k]                  = h0;
    *(__nv_bfloat162*)&base[j * LDA + k + 2]              = h1;
    *(__nv_bfloat162*)&base[TILE_ELEMS + j * LDA + k]     = l0;
    *(__nv_bfloat162*)&base[TILE_ELEMS + j * LDA + k + 2] = l1;
}

// ---------------- mean aggregation: warp per node, CSR gather ----------------
// Writes mean as bf16 hi/lo straight into the GEMM's per-tile blob layout.
__global__ void aggregate_kernel(const float* __restrict__ x,
                                 __nv_bfloat16* __restrict__ blob) {
    int w = (blockIdx.x * blockDim.x + threadIdx.x) >> 5;
    int lane = threadIdx.x & 31;
    if (w >= N_NODES) return;
    int beg = g_row[w];
    int end = g_row[w + 1];
    float4 s = make_float4(0.f, 0.f, 0.f, 0.f);
    for (int i = beg; i < end; i++) {
        int sn = g_csr[i];
        float4 v = *(const float4*)(x + (size_t)sn * HID + lane * 4);
        s.x += v.x; s.y += v.y; s.z += v.z; s.w += v.w;
    }
    float ic = 1.0f / fmaxf((float)(end - beg), 1.0f);
    s.x *= ic; s.y *= ic; s.z *= ic; s.w *= ic;
    __nv_bfloat162 h0 = __floats2bfloat162_rn(s.x, s.y);
    __nv_bfloat162 h1 = __floats2bfloat162_rn(s.z, s.w);
    float2 f0 = __bfloat1622float2(h0);
    float2 f1 = __bfloat1622float2(h1);
    __nv_bfloat162 l0 = __floats2bfloat162_rn(s.x - f0.x, s.y - f0.y);
    __nv_bfloat162 l1 = __floats2bfloat162_rn(s.z - f1.x, s.w - f1.y);
    __nv_bfloat16* base = blob + (size_t)(w >> 7) * 2 * TILE_ELEMS;
    int o = (w & 127) * LDA + lane * 4;
    *(__nv_bfloat162*)&base[o]                  = h0;
    *(__nv_bfloat162*)&base[o + 2]              = h1;
    *(__nv_bfloat162*)&base[TILE_ELEMS + o]     = l0;
    *(__nv_bfloat162*)&base[TILE_ELEMS + o + 2] = l1;
}

// ---------------- wmma (HMMA) fused dual GEMM, bf16x3 emulation -------------
// out = relu(mean @ Wl^T + x @ Wr^T + b), fp32 accumulators.
// mean side: A frags straight from the global A blob (L1).
// B: hi plane staged in smem (used 2x per MMA step), lo plane from global L1.
// smem = x-side A hi/lo + BH = 104448 B -> 2 CTAs/SM.
__global__ __launch_bounds__(256, 2) void gemm_wmma_kernel(
    const float* __restrict__ xin,
    const __nv_bfloat16* __restrict__ Ablob,   // all tiles
    const __nv_bfloat16* __restrict__ Wblob,   // layer base: [side][BH;BL]
    const float* __restrict__ bias, float* __restrict__ xout)
{
    extern __shared__ __nv_bfloat16 sm[];
    const int tid = threadIdx.x;
    const int wid = tid >> 5;
    const int wr = wid >> 1;            // warp row group (0..3)
    const int wc = wid & 1;             // warp col group (0..1)
    const int row0 = blockIdx.x * 128;
    const __nv_bfloat16* AmH = Ablob + (size_t)blockIdx.x * 2 * TILE_ELEMS;
    const __nv_bfloat16* AmL = AmH + TILE_ELEMS;

    wmma::fragment<wmma::accumulator, 16, 16, 16, float> acc[2][4];
#pragma unroll
    for (int i = 0; i < 2; i++)
#pragma unroll
        for (int j = 0; j < 4; j++) wmma::fill_fragment(acc[i][j], 0.0f);

    for (int side = 0; side < 2; side++) {
        const __nv_bfloat16* BH = Wblob + (size_t)side * 2 * TILE_ELEMS;
        const __nv_bfloat16* BL = BH + TILE_ELEMS;
        __syncthreads();   // previous side's smem fully consumed

        // stage BH plane: straight uint4 copy (34816 B)
        {
            const uint4* wsrc = (const uint4*)BH;
            uint4* wdst = (uint4*)(sm + SM_BH);
            for (int i = tid; i < 2176; i += 256) wdst[i] = wsrc[i];
        }
        // stage A only for x side (mean side reads the global blob directly)
        if (side == 1) {
            for (int i = tid; i < 128 * 32; i += 256) {
                int r = i >> 5;
                int c = (i & 31) << 2;
                int gr = row0 + r;
                float4 v = make_float4(0.f, 0.f, 0.f, 0.f);
                if (gr < N_NODES) v = *(const float4*)(xin + (size_t)gr * HID + c);
                __nv_bfloat162 h0 = __floats2bfloat162_rn(v.x, v.y);
                __nv_bfloat162 h1 = __floats2bfloat162_rn(v.z, v.w);
                float2 f0 = __bfloat1622float2(h0);
                float2 f1 = __bfloat1622float2(h1);
                __nv_bfloat162 l0 = __floats2bfloat162_rn(v.x - f0.x, v.y - f0.y);
                __nv_bfloat162 l1 = __floats2bfloat162_rn(v.z - f1.x, v.w - f1.y);
                int o = r * LDA + c;
                *(__nv_bfloat162*)&sm[SM_AH + o]     = h0;
                *(__nv_bfloat162*)&sm[SM_AH + o + 2] = h1;
                *(__nv_bfloat162*)&sm[SM_AL + o]     = l0;
                *(__nv_bfloat162*)&sm[SM_AL + o + 2] = l1;
            }
        }
        __syncthreads();

        for (int k = 0; k < HID; k += 16) {
            wmma::fragment<wmma::matrix_a, 16, 16, 16, __nv_bfloat16, wmma::row_major> ah[2], al[2];
            wmma::fragment<wmma::matrix_b, 16, 16, 16, __nv_bfloat16, wmma::col_major> bh[4], bl[4];
#pragma unroll
            for (int i = 0; i < 2; i++) {
                int r = wr * 32 + i * 16;
                if (side == 0) {
                    wmma::load_matrix_sync(ah[i], &AmH[r * LDA + k], LDA);   // global (L1)
                    wmma::load_matrix_sync(al[i], &AmL[r * LDA + k], LDA);   // global (L1)
                } else {
                    wmma::load_matrix_sync(ah[i], &sm[SM_AH + r * LDA + k], LDA);
                    wmma::load_matrix_sync(al[i], &sm[SM_AL + r * LDA + k], LDA);
                }
            }
#pragma unroll
            for (int j = 0; j < 4; j++) {
                int cj = wc * 64 + j * 16;
                wmma::load_matrix_sync(bh[j], &sm[SM_BH + cj * LDA + k], LDA);  // smem
                wmma::load_matrix_sync(bl[j], &BL[cj * LDA + k], LDA);          // global (L1)
            }
#pragma unroll
            for (int i = 0; i < 2; i++)
#pragma unroll
                for (int j = 0; j < 4; j++) {
                    wmma::mma_sync(acc[i][j], ah[i], bh[j], acc[i][j]);
                    wmma::mma_sync(acc[i][j], ah[i], bl[j], acc[i][j]);
                    wmma::mma_sync(acc[i][j], al[i], bh[j], acc[i][j]);
                }
        }
    }

    // epilogue: stage C in smem (reuse A planes), then bias + relu + store
    __syncthreads();
    float* Csm = (float*)sm;
#pragma unroll
    for (int i = 0; i < 2; i++)
#pragma unroll
        for (int j = 0; j < 4; j++) {
            int r = wr * 32 + i * 16;
            int c = wc * 64 + j * 16;
            wmma::store_matrix_sync(&Csm[r * LDC + c], acc[i][j], LDC, wmma::mem_row_major);
        }
    __syncthreads();

    for (int i = tid; i < 128 * 32; i += 256) {
        int r = i >> 5;
        int c = (i & 31) << 2;
        int gr = row0 + r;
        if (gr < N_NODES) {
            float4 v = *(const float4*)&Csm[r * LDC + c];
            float4 bv = *(const float4*)(bias + c);
            float4 o;
            o.x = fmaxf(v.x + bv.x, 0.f);
            o.y = fmaxf(v.y + bv.y, 0.f);
            o.z = fmaxf(v.z + bv.z, 0.f);
            o.w = fmaxf(v.w + bv.w, 0.f);
            *(float4*)(xout + (size_t)gr * HID + c) = o;
        }
    }
}

// ---------------- global add pool: block per graph (batch is SORTED) --------
__global__ void pool_kernel(const float* __restrict__ x, const int* __restrict__ batch,
                            float* __restrict__ pool) {
    __shared__ int s_beg, s_end;
    int g = blockIdx.x;
    int t = threadIdx.x;
    if (t == 0) {
        int lo = 0, hi = N_NODES;
        while (lo < hi) { int m = (lo + hi) >> 1; if (batch[m] < g) lo = m + 1; else hi = m; }
        s_beg = lo;
    }
    if (t == 1) {
        int lo = 0, hi = N_NODES;
        while (lo < hi) { int m = (lo + hi) >> 1; if (batch[m] < g + 1) lo = m + 1; else hi = m; }
        s_end = lo;
    }
    __syncthreads();
    int beg = s_beg, end = s_end;
    float s = 0.0f;
    for (int n = beg; n < end; n++) s += x[(size_t)n * HID + t];
    pool[(size_t)g * HID + t] = s;
}

// ---------------- MLP head + log_softmax: block per graph ----------------
__global__ void mlp_kernel(const float* __restrict__ pool,
                           const float* __restrict__ W1, const float* __restrict__ b1,
                           const float* __restrict__ W2, const float* __restrict__ b2,
                           float* __restrict__ out) {
    __shared__ float sg[HID];
    __shared__ float sh[HID];
    __shared__ float sl[N_CLASSES];
    int gph = blockIdx.x;
    int t = threadIdx.x;

    sg[t] = fmaxf(pool[(size_t)gph * HID + t], 0.0f);
    __syncthreads();

    float acc = b1[t];
    const float* w1r = W1 + (size_t)t * HID;
#pragma unroll 8
    for (int k = 0; k < HID; k++) acc += sg[k] * w1r[k];
    sh[t] = fmaxf(acc, 0.0f);
    __syncthreads();

    if (t < N_CLASSES) {
        float a = b2[t];
        const float* w2r = W2 + (size_t)t * HID;
#pragma unroll 8
        for (int k = 0; k < HID; k++) a += sh[k] * w2r[k];
        sl[t] = a;
    }
    __syncthreads();

    if (t == 0) {
        float m = -1e30f;
        for (int c = 0; c < N_CLASSES; c++) m = fmaxf(m, sl[c]);
        float s = 0.0f;
        for (int c = 0; c < N_CLASSES; c++) s += expf(sl[c] - m);
        float lse = m + logf(s);
        for (int c = 0; c < N_CLASSES; c++) out[(size_t)gph * N_CLASSES + c] = sl[c] - lse;
    }
}

// ---------------- launch ----------------
extern "C" void kernel_launch(void* const* d_in, const int* in_sizes, int n_in,
                              void* d_out, int out_size) {
    const float* x     = (const float*)d_in[0];
    // d_in[1] = edge_attr (ignored by SAGEConv)
    const int*   ei    = (const int*)d_in[2];
    const int*   srcE  = ei;
    const int*   dstE  = ei + N_EDGES;
    const int*   batch = (const int*)d_in[3];
    const float* Wl    = (const float*)d_in[4];
    const float* bl    = (const float*)d_in[5];
    const float* Wr    = (const float*)d_in[6];
    const float* W1    = (const float*)d_in[7];
    const float* b1    = (const float*)d_in[8];
    const float* W2    = (const float*)d_in[9];
    const float* b2    = (const float*)d_in[10];
    float* out = (float*)d_out;

    int *p_cnt, *p_row, *p_tmp, *p_csr, *p_bsum, *p_boff;
    float *p_h0, *p_h1, *p_pool;
    __nv_bfloat16 *p_ablob, *p_wblob;
    cudaGetSymbolAddress((void**)&p_cnt, g_cnt);
    cudaGetSymbolAddress((void**)&p_row, g_row);
    cudaGetSymbolAddress((void**)&p_tmp, g_tmp);
    cudaGetSymbolAddress((void**)&p_csr, g_csr);
    cudaGetSymbolAddress((void**)&p_bsum, g_bsum);
    cudaGetSymbolAddress((void**)&p_boff, g_boff);
    cudaGetSymbolAddress((void**)&p_h0, g_h0);
    cudaGetSymbolAddress((void**)&p_h1, g_h1);
    cudaGetSymbolAddress((void**)&p_pool, g_pool);
    cudaGetSymbolAddress((void**)&p_ablob, g_Ablob);
    cudaGetSymbolAddress((void**)&p_wblob, g_Wblob);

    static int smem_set = 0;
    if (!smem_set) {
        cudaFuncSetAttribute(gemm_wmma_kernel,
                             cudaFuncAttributeMaxDynamicSharedMemorySize, GEMM_SMEM);
        smem_set = 1;
    }

    const int TB = 256;
    const int edge_blocks = (N_EDGES + TB - 1) / TB;
    const int warp_node_blocks = (N_NODES * 32 + TB - 1) / TB;

    // CSR build (reused by all 3 layers)
    cudaMemsetAsync(p_cnt, 0, N_NODES * sizeof(int), 0);
    count_kernel<<<edge_blocks, TB>>>(dstE, p_cnt, N_EDGES);
    scan_partial_kernel<<<SCAN_NB, SCAN_B>>>(p_cnt, p_bsum);
    scan_bsum_kernel<<<1, 128>>>(p_bsum, p_boff);
    scan_apply_kernel<<<SCAN_NB, SCAN_B>>>(p_cnt, p_boff, p_row, p_tmp);
    fill_csr_kernel<<<edge_blocks, TB>>>(srcE, dstE, p_tmp, p_csr, N_EDGES);

    // precompute W hi/lo blobs (padded-LDA image)
    prep_w_kernel<<<(N_LAYERS * 2 * 128 * 32 + TB - 1) / TB, TB>>>(Wl, Wr, p_wblob);

    const float* cur = x;
    float* bufs[2] = {p_h0, p_h1};
    for (int l = 0; l < N_LAYERS; l++) {
        aggregate_kernel<<<warp_node_blocks, TB>>>(cur, p_ablob);
        gemm_wmma_kernel<<<N_TILES, TB, GEMM_SMEM>>>(
            cur, p_ablob, p_wblob + (size_t)(l * 2) * 2 * TILE_ELEMS,
            bl + l * HID, bufs[l & 1]);
        cur = bufs[l & 1];
    }

    pool_kernel<<<N_GRAPHS, HID>>>(cur, batch, p_pool);
    mlp_kernel<<<N_GRAPHS, HID>>>(p_pool, W1, b1, W2, b2, out);
}

// round 14
// speedup vs baseline: 1.1129x; 1.1129x over previous
#include <cuda_runtime.h>
#include <cuda_bf16.h>
#include <mma.h>
#include <math.h>
#include <stdint.h>

using namespace nvcuda;

#define N_NODES 50000
#define N_EDGES 600000
#define N_GRAPHS 500
#define HID 128
#define N_LAYERS 3
#define N_CLASSES 10

#define SCAN_B 512
#define SCAN_NB ((N_NODES + SCAN_B - 1) / SCAN_B)   // 98

#define LDA 136                       // bf16 stride (pad 8 halves = 16B)
#define LDC 132                       // fp32 epilogue stride
#define TILE_ELEMS (128 * LDA)        // 17408 bf16 per plane
#define SM_AH 0
#define SM_AL TILE_ELEMS
#define SM_BH (2 * TILE_ELEMS)
#define GEMM_SMEM (3 * TILE_ELEMS * 2)   // 104448 B -> 2 CTAs/SM

// ---------------- scratch (device globals; no allocs allowed) ----------------
__device__ int   g_cnt[N_NODES];
__device__ int   g_row[N_NODES + 1];
__device__ int   g_tmp[N_NODES];
__device__ int   g_csr[N_EDGES];
__device__ int   g_bsum[SCAN_NB];
__device__ int   g_boff[SCAN_NB];
__device__ float g_mean[(size_t)N_NODES * HID];
__device__ float g_h0[(size_t)N_NODES * HID];
__device__ float g_h1[(size_t)N_NODES * HID];
__device__ float g_pool[N_GRAPHS * HID];
// W hi/lo blobs in padded-LDA layout: [layer][side][BH ; BL] bf16
__device__ __align__(16) __nv_bfloat16 g_Wblob[(size_t)N_LAYERS * 2 * 2 * TILE_ELEMS];

// ---------------- tiny utility kernels ----------------
__global__ void count_kernel(const int* __restrict__ dst, int* __restrict__ cnt, int nE) {
    int i = blockIdx.x * blockDim.x + threadIdx.x;
    if (i < nE) atomicAdd(&cnt[dst[i]], 1);
}

__global__ void scan_partial_kernel(const int* __restrict__ cnt, int* __restrict__ bsum) {
    __shared__ int sh[SCAN_B];
    int t = threadIdx.x;
    int i = blockIdx.x * SCAN_B + t;
    sh[t] = (i < N_NODES) ? cnt[i] : 0;
    __syncthreads();
#pragma unroll
    for (int off = SCAN_B / 2; off > 0; off >>= 1) {
        if (t < off) sh[t] += sh[t + off];
        __syncthreads();
    }
    if (t == 0) bsum[blockIdx.x] = sh[0];
}

__global__ void scan_bsum_kernel(const int* __restrict__ bsum, int* __restrict__ boff) {
    __shared__ int sh[128];
    int t = threadIdx.x;
    int v = (t < SCAN_NB) ? bsum[t] : 0;
    sh[t] = v;
    __syncthreads();
#pragma unroll
    for (int off = 1; off < 128; off <<= 1) {
        int add = (t >= off) ? sh[t - off] : 0;
        __syncthreads();
        sh[t] += add;
        __syncthreads();
    }
    if (t < SCAN_NB) boff[t] = sh[t] - v;
}

__global__ void scan_apply_kernel(const int* __restrict__ cnt, const int* __restrict__ boff,
                                  int* __restrict__ row, int* __restrict__ tmp) {
    __shared__ int sh[SCAN_B];
    int t = threadIdx.x;
    int i = blockIdx.x * SCAN_B + t;
    int v = (i < N_NODES) ? cnt[i] : 0;
    sh[t] = v;
    __syncthreads();
#pragma unroll
    for (int off = 1; off < SCAN_B; off <<= 1) {
        int add = (t >= off) ? sh[t - off] : 0;
        __syncthreads();
        sh[t] += add;
        __syncthreads();
    }
    int excl = boff[blockIdx.x] + sh[t] - v;
    if (i < N_NODES) { row[i] = excl; tmp[i] = excl; }
    if (i == N_NODES - 1) row[N_NODES] = excl + v;
}

__global__ void fill_csr_kernel(const int* __restrict__ src, const int* __restrict__ dst,
                                int* __restrict__ tmp, int* __restrict__ csr, int nE) {
    int i = blockIdx.x * blockDim.x + threadIdx.x;
    if (i < nE) {
        int p = atomicAdd(&tmp[dst[i]], 1);
        csr[p] = src[i];
    }
}

// ---------------- W prep: fp32 [j][k] -> bf16 hi/lo in padded-LDA layout -----
__global__ void prep_w_kernel(const float* __restrict__ Wl, const float* __restrict__ Wr,
                              __nv_bfloat16* __restrict__ blob) {
    int i = blockIdx.x * blockDim.x + threadIdx.x;   // one float4 per thread
    if (i >= N_LAYERS * 2 * 128 * 32) return;
    int kq   = i & 31;           // k/4
    int j    = (i >> 5) & 127;
    int side = (i >> 12) & 1;
    int l    = i >> 13;
    int k = kq << 2;
    const float* W = side ? Wr : Wl;
    float4 v = *(const float4*)(W + (size_t)l * 16384 + j * HID + k);
    __nv_bfloat162 h0 = __floats2bfloat162_rn(v.x, v.y);
    __nv_bfloat162 h1 = __floats2bfloat162_rn(v.z, v.w);
    float2 f0 = __bfloat1622float2(h0);
    float2 f1 = __bfloat1622float2(h1);
    __nv_bfloat162 l0 = __floats2bfloat162_rn(v.x - f0.x, v.y - f0.y);
    __nv_bfloat162 l1 = __floats2bfloat162_rn(v.z - f1.x, v.w - f1.y);
    __nv_bfloat16* base = blob + ((size_t)(l * 2 + side)) * 2 * TILE_ELEMS;
    *(__nv_bfloat162*)&base[j * LDA + k]                  = h0;
    *(__nv_bfloat162*)&base[j * LDA + k + 2]              = h1;
    *(__nv_bfloat162*)&base[TILE_ELEMS + j * LDA + k]     = l0;
    *(__nv_bfloat162*)&base[TILE_ELEMS + j * LDA + k + 2] = l1;
}

// ---------------- mean aggregation: warp per node, CSR gather ----------------
__global__ void aggregate_kernel(const float* __restrict__ x, float* __restrict__ mean) {
    int w = (blockIdx.x * blockDim.x + threadIdx.x) >> 5;
    int lane = threadIdx.x & 31;
    if (w >= N_NODES) return;
    int beg = g_row[w];
    int end = g_row[w + 1];
    float4 s = make_float4(0.f, 0.f, 0.f, 0.f);
    for (int i = beg; i < end; i++) {
        int sn = g_csr[i];
        float4 v = *(const float4*)(x + (size_t)sn * HID + lane * 4);
        s.x += v.x; s.y += v.y; s.z += v.z; s.w += v.w;
    }
    float ic = 1.0f / fmaxf((float)(end - beg), 1.0f);
    s.x *= ic; s.y *= ic; s.z *= ic; s.w *= ic;
    *(float4*)(mean + (size_t)w * HID + lane * 4) = s;
}

// ---------------- wmma (HMMA) fused dual GEMM, bf16x3 emulation -------------
// out = relu(mean @ Wl^T + x @ Wr^T + b), fp32 accumulators.
// A (both sides) and BH staged in smem (LDSM path); BL from global (L1).
// smem = 104448 B -> 2 CTAs/SM.
__global__ __launch_bounds__(256, 2) void gemm_wmma_kernel(
    const float* __restrict__ xin, const float* __restrict__ mean,
    const __nv_bfloat16* __restrict__ Wblob,   // layer base: [side][BH;BL]
    const float* __restrict__ bias, float* __restrict__ xout)
{
    extern __shared__ __nv_bfloat16 sm[];
    const int tid = threadIdx.x;
    const int wid = tid >> 5;
    const int wr = wid >> 1;            // warp row group (0..3)
    const int wc = wid & 1;             // warp col group (0..1)
    const int row0 = blockIdx.x * 128;

    wmma::fragment<wmma::accumulator, 16, 16, 16, float> acc[2][4];
#pragma unroll
    for (int i = 0; i < 2; i++)
#pragma unroll
        for (int j = 0; j < 4; j++) wmma::fill_fragment(acc[i][j], 0.0f);

    for (int side = 0; side < 2; side++) {
        const float* A = side ? xin : mean;
        const __nv_bfloat16* BH = Wblob + (size_t)side * 2 * TILE_ELEMS;
        const __nv_bfloat16* BL = BH + TILE_ELEMS;
        __syncthreads();   // previous side's smem fully consumed

        // stage BH plane: straight uint4 copy (34816 B)
        {
            const uint4* wsrc = (const uint4*)BH;
            uint4* wdst = (uint4*)(sm + SM_BH);
            for (int i = tid; i < 2176; i += 256) wdst[i] = wsrc[i];
        }
        // stage A: 128 rows x 128 cols fp32 -> bf16 hi/lo
        for (int i = tid; i < 128 * 32; i += 256) {
            int r = i >> 5;
            int c = (i & 31) << 2;
            int gr = row0 + r;
            float4 v = make_float4(0.f, 0.f, 0.f, 0.f);
            if (gr < N_NODES) v = *(const float4*)(A + (size_t)gr * HID + c);
            __nv_bfloat162 h0 = __floats2bfloat162_rn(v.x, v.y);
            __nv_bfloat162 h1 = __floats2bfloat162_rn(v.z, v.w);
            float2 f0 = __bfloat1622float2(h0);
            float2 f1 = __bfloat1622float2(h1);
            __nv_bfloat162 l0 = __floats2bfloat162_rn(v.x - f0.x, v.y - f0.y);
            __nv_bfloat162 l1 = __floats2bfloat162_rn(v.z - f1.x, v.w - f1.y);
            int o = r * LDA + c;
            *(__nv_bfloat162*)&sm[SM_AH + o]     = h0;
            *(__nv_bfloat162*)&sm[SM_AH + o + 2] = h1;
            *(__nv_bfloat162*)&sm[SM_AL + o]     = l0;
            *(__nv_bfloat162*)&sm[SM_AL + o + 2] = l1;
        }
        __syncthreads();

        for (int k = 0; k < HID; k += 16) {
            wmma::fragment<wmma::matrix_a, 16, 16, 16, __nv_bfloat16, wmma::row_major> ah[2], al[2];
            wmma::fragment<wmma::matrix_b, 16, 16, 16, __nv_bfloat16, wmma::col_major> bh[4], bl[4];
#pragma unroll
            for (int i = 0; i < 2; i++) {
                int r = wr * 32 + i * 16;
                wmma::load_matrix_sync(ah[i], &sm[SM_AH + r * LDA + k], LDA);
                wmma::load_matrix_sync(al[i], &sm[SM_AL + r * LDA + k], LDA);
            }
#pragma unroll
            for (int j = 0; j < 4; j++) {
                int cj = wc * 64 + j * 16;
                wmma::load_matrix_sync(bh[j], &sm[SM_BH + cj * LDA + k], LDA);  // smem
                wmma::load_matrix_sync(bl[j], &BL[cj * LDA + k], LDA);          // global (L1)
            }
#pragma unroll
            for (int i = 0; i < 2; i++)
#pragma unroll
                for (int j = 0; j < 4; j++) {
                    wmma::mma_sync(acc[i][j], ah[i], bh[j], acc[i][j]);
                    wmma::mma_sync(acc[i][j], ah[i], bl[j], acc[i][j]);
                    wmma::mma_sync(acc[i][j], al[i], bh[j], acc[i][j]);
                }
        }
    }

    // epilogue: stage C in smem (reuse A planes), then bias + relu + store
    __syncthreads();
    float* Csm = (float*)sm;
#pragma unroll
    for (int i = 0; i < 2; i++)
#pragma unroll
        for (int j = 0; j < 4; j++) {
            int r = wr * 32 + i * 16;
            int c = wc * 64 + j * 16;
            wmma::store_matrix_sync(&Csm[r * LDC + c], acc[i][j], LDC, wmma::mem_row_major);
        }
    __syncthreads();

    for (int i = tid; i < 128 * 32; i += 256) {
        int r = i >> 5;
        int c = (i & 31) << 2;
        int gr = row0 + r;
        if (gr < N_NODES) {
            float4 v = *(const float4*)&Csm[r * LDC + c];
            float4 bv = *(const float4*)(bias + c);
            float4 o;
            o.x = fmaxf(v.x + bv.x, 0.f);
            o.y = fmaxf(v.y + bv.y, 0.f);
            o.z = fmaxf(v.z + bv.z, 0.f);
            o.w = fmaxf(v.w + bv.w, 0.f);
            *(float4*)(xout + (size_t)gr * HID + c) = o;
        }
    }
}

// ---------------- global add pool: block per graph (batch is SORTED) --------
__global__ void pool_kernel(const float* __restrict__ x, const int* __restrict__ batch,
                            float* __restrict__ pool) {
    __shared__ int s_beg, s_end;
    int g = blockIdx.x;
    int t = threadIdx.x;
    if (t == 0) {
        int lo = 0, hi = N_NODES;
        while (lo < hi) { int m = (lo + hi) >> 1; if (batch[m] < g) lo = m + 1; else hi = m; }
        s_beg = lo;
    }
    if (t == 1) {
        int lo = 0, hi = N_NODES;
        while (lo < hi) { int m = (lo + hi) >> 1; if (batch[m] < g + 1) lo = m + 1; else hi = m; }
        s_end = lo;
    }
    __syncthreads();
    int beg = s_beg, end = s_end;
    float s = 0.0f;
    for (int n = beg; n < end; n++) s += x[(size_t)n * HID + t];
    pool[(size_t)g * HID + t] = s;
}

// ---------------- MLP head + log_softmax: block per graph ----------------
__global__ void mlp_kernel(const float* __restrict__ pool,
                           const float* __restrict__ W1, const float* __restrict__ b1,
                           const float* __restrict__ W2, const float* __restrict__ b2,
                           float* __restrict__ out) {
    __shared__ float sg[HID];
    __shared__ float sh[HID];
    __shared__ float sl[N_CLASSES];
    int gph = blockIdx.x;
    int t = threadIdx.x;

    sg[t] = fmaxf(pool[(size_t)gph * HID + t], 0.0f);
    __syncthreads();

    float acc = b1[t];
    const float* w1r = W1 + (size_t)t * HID;
#pragma unroll 8
    for (int k = 0; k < HID; k++) acc += sg[k] * w1r[k];
    sh[t] = fmaxf(acc, 0.0f);
    __syncthreads();

    if (t < N_CLASSES) {
        float a = b2[t];
        const float* w2r = W2 + (size_t)t * HID;
#pragma unroll 8
        for (int k = 0; k < HID; k++) a += sh[k] * w2r[k];
        sl[t] = a;
    }
    __syncthreads();

    if (t == 0) {
        float m = -1e30f;
        for (int c = 0; c < N_CLASSES; c++) m = fmaxf(m, sl[c]);
        float s = 0.0f;
        for (int c = 0; c < N_CLASSES; c++) s += expf(sl[c] - m);
        float lse = m + logf(s);
        for (int c = 0; c < N_CLASSES; c++) out[(size_t)gph * N_CLASSES + c] = sl[c] - lse;
    }
}

// ---------------- launch ----------------
extern "C" void kernel_launch(void* const* d_in, const int* in_sizes, int n_in,
                              void* d_out, int out_size) {
    const float* x     = (const float*)d_in[0];
    // d_in[1] = edge_attr (ignored by SAGEConv)
    const int*   ei    = (const int*)d_in[2];
    const int*   srcE  = ei;
    const int*   dstE  = ei + N_EDGES;
    const int*   batch = (const int*)d_in[3];
    const float* Wl    = (const float*)d_in[4];
    const float* bl    = (const float*)d_in[5];
    const float* Wr    = (const float*)d_in[6];
    const float* W1    = (const float*)d_in[7];
    const float* b1    = (const float*)d_in[8];
    const float* W2    = (const float*)d_in[9];
    const float* b2    = (const float*)d_in[10];
    float* out = (float*)d_out;

    int *p_cnt, *p_row, *p_tmp, *p_csr, *p_bsum, *p_boff;
    float *p_mean, *p_h0, *p_h1, *p_pool;
    __nv_bfloat16* p_wblob;
    cudaGetSymbolAddress((void**)&p_cnt, g_cnt);
    cudaGetSymbolAddress((void**)&p_row, g_row);
    cudaGetSymbolAddress((void**)&p_tmp, g_tmp);
    cudaGetSymbolAddress((void**)&p_csr, g_csr);
    cudaGetSymbolAddress((void**)&p_bsum, g_bsum);
    cudaGetSymbolAddress((void**)&p_boff, g_boff);
    cudaGetSymbolAddress((void**)&p_mean, g_mean);
    cudaGetSymbolAddress((void**)&p_h0, g_h0);
    cudaGetSymbolAddress((void**)&p_h1, g_h1);
    cudaGetSymbolAddress((void**)&p_pool, g_pool);
    cudaGetSymbolAddress((void**)&p_wblob, g_Wblob);

    static int smem_set = 0;
    if (!smem_set) {
        cudaFuncSetAttribute(gemm_wmma_kernel,
                             cudaFuncAttributeMaxDynamicSharedMemorySize, GEMM_SMEM);
        smem_set = 1;
    }

    const int TB = 256;
    const int edge_blocks = (N_EDGES + TB - 1) / TB;
    const int warp_node_blocks = (N_NODES * 32 + TB - 1) / TB;
    const int gemm_blocks = (N_NODES + 127) / 128;   // 391

    // CSR build (reused by all 3 layers)
    cudaMemsetAsync(p_cnt, 0, N_NODES * sizeof(int), 0);
    count_kernel<<<edge_blocks, TB>>>(dstE, p_cnt, N_EDGES);
    scan_partial_kernel<<<SCAN_NB, SCAN_B>>>(p_cnt, p_bsum);
    scan_bsum_kernel<<<1, 128>>>(p_bsum, p_boff);
    scan_apply_kernel<<<SCAN_NB, SCAN_B>>>(p_cnt, p_boff, p_row, p_tmp);
    fill_csr_kernel<<<edge_blocks, TB>>>(srcE, dstE, p_tmp, p_csr, N_EDGES);

    // precompute W hi/lo blobs (padded-LDA image)
    prep_w_kernel<<<(N_LAYERS * 2 * 128 * 32 + TB - 1) / TB, TB>>>(Wl, Wr, p_wblob);

    const float* cur = x;
    float* bufs[2] = {p_h0, p_h1};
    for (int l = 0; l < N_LAYERS; l++) {
        aggregate_kernel<<<warp_node_blocks, TB>>>(cur, p_mean);
        gemm_wmma_kernel<<<gemm_blocks, TB, GEMM_SMEM>>>(
            cur, p_mean, p_wblob + (size_t)(l * 2) * 2 * TILE_ELEMS,
            bl + l * HID, bufs[l & 1]);
        cur = bufs[l & 1];
    }

    pool_kernel<<<N_GRAPHS, HID>>>(cur, batch, p_pool);
    mlp_kernel<<<N_GRAPHS, HID>>>(p_pool, W1, b1, W2, b2, out);
}

// round 15
// speedup vs baseline: 1.1269x; 1.0126x over previous
#include <cuda_runtime.h>
#include <cuda_bf16.h>
#include <mma.h>
#include <math.h>
#include <stdint.h>

using namespace nvcuda;

#define N_NODES 50000
#define N_PAD 50048                   // padded for direct wmma stores
#define N_EDGES 600000
#define N_GRAPHS 500
#define HID 128
#define N_LAYERS 3
#define N_CLASSES 10

#define SCAN_B 512
#define SCAN_NB ((N_NODES + SCAN_B - 1) / SCAN_B)   // 98

#define LDA 136                       // bf16 stride (pad 8 halves = 16B)
#define TILE_ELEMS (128 * LDA)        // 17408 bf16 per plane
#define SM_AH 0
#define SM_AL TILE_ELEMS
#define SM_BH (2 * TILE_ELEMS)
#define GEMM_SMEM (3 * TILE_ELEMS * 2)   // 104448 B -> 2 CTAs/SM

// ---------------- scratch (device globals; no allocs allowed) ----------------
__device__ int   g_cnt[N_NODES];
__device__ int   g_row[N_NODES + 1];
__device__ int   g_tmp[N_NODES];
__device__ int   g_csr[N_EDGES];
__device__ int   g_bsum[SCAN_NB];
__device__ float g_mean[(size_t)N_PAD * HID];
__device__ float g_h0[(size_t)N_PAD * HID];
__device__ float g_h1[(size_t)N_PAD * HID];
__device__ float g_pool[N_GRAPHS * HID];
// W hi/lo blobs in padded-LDA layout: [layer][side][BH ; BL] bf16
__device__ __align__(16) __nv_bfloat16 g_Wblob[(size_t)N_LAYERS * 2 * 2 * TILE_ELEMS];
// bias tiles: [layer][16 rows][128 cols], rows replicated
__device__ __align__(16) float g_btile[N_LAYERS * 16 * HID];

// ---------------- tiny utility kernels ----------------
__global__ void count_kernel(const int* __restrict__ dst, int* __restrict__ cnt, int nE) {
    int i = blockIdx.x * blockDim.x + threadIdx.x;
    if (i < nE) atomicAdd(&cnt[dst[i]], 1);
}

__global__ void scan_partial_kernel(const int* __restrict__ cnt, int* __restrict__ bsum) {
    __shared__ int sh[SCAN_B];
    int t = threadIdx.x;
    int i = blockIdx.x * SCAN_B + t;
    sh[t] = (i < N_NODES) ? cnt[i] : 0;
    __syncthreads();
#pragma unroll
    for (int off = SCAN_B / 2; off > 0; off >>= 1) {
        if (t < off) sh[t] += sh[t + off];
        __syncthreads();
    }
    if (t == 0) bsum[blockIdx.x] = sh[0];
}

// fused: per-block offset from bsum + local scan + row/tmp write
__global__ void scan_apply_kernel(const int* __restrict__ cnt, const int* __restrict__ bsum,
                                  int* __restrict__ row, int* __restrict__ tmp) {
    __shared__ int sh[SCAN_B];
    __shared__ int sb[128];
    __shared__ int s_boff;
    int t = threadIdx.x;
    int i = blockIdx.x * SCAN_B + t;

    // block offset = sum of bsum[0..blockIdx.x)
    if (t < 128) sb[t] = (t < blockIdx.x && t < SCAN_NB) ? bsum[t] : 0;
    __syncthreads();
    if (t < 64) sb[t] += sb[t + 64];
    __syncthreads();
    if (t < 32) {
        int v = sb[t] + sb[t + 32];
#pragma unroll
        for (int off = 16; off > 0; off >>= 1)
            v += __shfl_down_sync(0xFFFFFFFF, v, off);
        if (t == 0) s_boff = v;
    }

    int v = (i < N_NODES) ? cnt[i] : 0;
    sh[t] = v;
    __syncthreads();
#pragma unroll
    for (int off = 1; off < SCAN_B; off <<= 1) {
        int add = (t >= off) ? sh[t - off] : 0;
        __syncthreads();
        sh[t] += add;
        __syncthreads();
    }
    int excl = s_boff + sh[t] - v;
    if (i < N_NODES) { row[i] = excl; tmp[i] = excl; }
    if (i == N_NODES - 1) row[N_NODES] = excl + v;
}

__global__ void fill_csr_kernel(const int* __restrict__ src, const int* __restrict__ dst,
                                int* __restrict__ tmp, int* __restrict__ csr, int nE) {
    int i = blockIdx.x * blockDim.x + threadIdx.x;
    if (i < nE) {
        int p = atomicAdd(&tmp[dst[i]], 1);
        csr[p] = src[i];
    }
}

// ---------------- W prep: fp32 [j][k] -> bf16 hi/lo in padded-LDA layout -----
__global__ void prep_w_kernel(const float* __restrict__ Wl, const float* __restrict__ Wr,
                              __nv_bfloat16* __restrict__ blob) {
    int i = blockIdx.x * blockDim.x + threadIdx.x;   // one float4 per thread
    if (i >= N_LAYERS * 2 * 128 * 32) return;
    int kq   = i & 31;           // k/4
    int j    = (i >> 5) & 127;
    int side = (i >> 12) & 1;
    int l    = i >> 13;
    int k = kq << 2;
    const float* W = side ? Wr : Wl;
    float4 v = *(const float4*)(W + (size_t)l * 16384 + j * HID + k);
    __nv_bfloat162 h0 = __floats2bfloat162_rn(v.x, v.y);
    __nv_bfloat162 h1 = __floats2bfloat162_rn(v.z, v.w);
    float2 f0 = __bfloat1622float2(h0);
    float2 f1 = __bfloat1622float2(h1);
    __nv_bfloat162 l0 = __floats2bfloat162_rn(v.x - f0.x, v.y - f0.y);
    __nv_bfloat162 l1 = __floats2bfloat162_rn(v.z - f1.x, v.w - f1.y);
    __nv_bfloat16* base = blob + ((size_t)(l * 2 + side)) * 2 * TILE_ELEMS;
    *(__nv_bfloat162*)&base[j * LDA + k]                  = h0;
    *(__nv_bfloat162*)&base[j * LDA + k + 2]              = h1;
    *(__nv_bfloat162*)&base[TILE_ELEMS + j * LDA + k]     = l0;
    *(__nv_bfloat162*)&base[TILE_ELEMS + j * LDA + k + 2] = l1;
}

// bias tiles: replicate bias row 16x per layer
__global__ void prep_bias_kernel(const float* __restrict__ bl, float* __restrict__ btile) {
    int i = blockIdx.x * blockDim.x + threadIdx.x;
    if (i >= N_LAYERS * 16 * HID) return;
    int c = i & 127;
    int l = i >> 11;
    btile[i] = bl[l * HID + c];
}

// ---------------- mean aggregation: warp per node, CSR gather ----------------
__global__ void aggregate_kernel(const float* __restrict__ x, float* __restrict__ mean) {
    int w = (blockIdx.x * blockDim.x + threadIdx.x) >> 5;
    int lane = threadIdx.x & 31;
    if (w >= N_NODES) return;
    int beg = g_row[w];
    int end = g_row[w + 1];
    float4 s = make_float4(0.f, 0.f, 0.f, 0.f);
    for (int i = beg; i < end; i++) {
        int sn = g_csr[i];
        float4 v = *(const float4*)(x + (size_t)sn * HID + lane * 4);
        s.x += v.x; s.y += v.y; s.z += v.z; s.w += v.w;
    }
    float ic = 1.0f / fmaxf((float)(end - beg), 1.0f);
    s.x *= ic; s.y *= ic; s.z *= ic; s.w *= ic;
    *(float4*)(mean + (size_t)w * HID + lane * 4) = s;
}

// ---------------- wmma (HMMA) fused dual GEMM, bf16x3 emulation -------------
// out = relu(mean @ Wl^T + x @ Wr^T + b), fp32 accumulators.
// Bias pre-loaded into accumulators; relu on fragments; direct global store.
__global__ __launch_bounds__(256, 2) void gemm_wmma_kernel(
    const float* __restrict__ xin, const float* __restrict__ mean,
    const __nv_bfloat16* __restrict__ Wblob,   // layer base: [side][BH;BL]
    const float* __restrict__ btile,           // [16][128] replicated bias
    float* __restrict__ xout)                  // padded to N_PAD rows
{
    extern __shared__ __nv_bfloat16 sm[];
    const int tid = threadIdx.x;
    const int wid = tid >> 5;
    const int wr = wid >> 1;            // warp row group (0..3)
    const int wc = wid & 1;             // warp col group (0..1)
    const int row0 = blockIdx.x * 128;

    // init accumulators with bias (rows of btile are identical)
    wmma::fragment<wmma::accumulator, 16, 16, 16, float> acc[2][4];
#pragma unroll
    for (int i = 0; i < 2; i++)
#pragma unroll
        for (int j = 0; j < 4; j++)
            wmma::load_matrix_sync(acc[i][j], btile + wc * 64 + j * 16, HID,
                                   wmma::mem_row_major);

    for (int side = 0; side < 2; side++) {
        const float* A = side ? xin : mean;
        const __nv_bfloat16* BH = Wblob + (size_t)side * 2 * TILE_ELEMS;
        const __nv_bfloat16* BL = BH + TILE_ELEMS;
        __syncthreads();   // previous side's smem fully consumed

        // stage BH plane: straight uint4 copy (34816 B)
        {
            const uint4* wsrc = (const uint4*)BH;
            uint4* wdst = (uint4*)(sm + SM_BH);
            for (int i = tid; i < 2176; i += 256) wdst[i] = wsrc[i];
        }
        // stage A: 128 rows x 128 cols fp32 -> bf16 hi/lo
        for (int i = tid; i < 128 * 32; i += 256) {
            int r = i >> 5;
            int c = (i & 31) << 2;
            int gr = row0 + r;
            float4 v = make_float4(0.f, 0.f, 0.f, 0.f);
            if (gr < N_NODES) v = *(const float4*)(A + (size_t)gr * HID + c);
            __nv_bfloat162 h0 = __floats2bfloat162_rn(v.x, v.y);
            __nv_bfloat162 h1 = __floats2bfloat162_rn(v.z, v.w);
            float2 f0 = __bfloat1622float2(h0);
            float2 f1 = __bfloat1622float2(h1);
            __nv_bfloat162 l0 = __floats2bfloat162_rn(v.x - f0.x, v.y - f0.y);
            __nv_bfloat162 l1 = __floats2bfloat162_rn(v.z - f1.x, v.w - f1.y);
            int o = r * LDA + c;
            *(__nv_bfloat162*)&sm[SM_AH + o]     = h0;
            *(__nv_bfloat162*)&sm[SM_AH + o + 2] = h1;
            *(__nv_bfloat162*)&sm[SM_AL + o]     = l0;
            *(__nv_bfloat162*)&sm[SM_AL + o + 2] = l1;
        }
        __syncthreads();

        for (int k = 0; k < HID; k += 16) {
            wmma::fragment<wmma::matrix_a, 16, 16, 16, __nv_bfloat16, wmma::row_major> ah[2], al[2];
            wmma::fragment<wmma::matrix_b, 16, 16, 16, __nv_bfloat16, wmma::col_major> bh[4], bl[4];
#pragma unroll
            for (int i = 0; i < 2; i++) {
                int r = wr * 32 + i * 16;
                wmma::load_matrix_sync(ah[i], &sm[SM_AH + r * LDA + k], LDA);
                wmma::load_matrix_sync(al[i], &sm[SM_AL + r * LDA + k], LDA);
            }
#pragma unroll
            for (int j = 0; j < 4; j++) {
                int cj = wc * 64 + j * 16;
                wmma::load_matrix_sync(bh[j], &sm[SM_BH + cj * LDA + k], LDA);  // smem
                wmma::load_matrix_sync(bl[j], &BL[cj * LDA + k], LDA);          // global (L1)
            }
#pragma unroll
            for (int i = 0; i < 2; i++)
#pragma unroll
                for (int j = 0; j < 4; j++) {
                    wmma::mma_sync(acc[i][j], ah[i], bh[j], acc[i][j]);
                    wmma::mma_sync(acc[i][j], ah[i], bl[j], acc[i][j]);
                    wmma::mma_sync(acc[i][j], al[i], bh[j], acc[i][j]);
                }
        }
    }

    // epilogue: relu on fragments, direct global store (padded buffer)
#pragma unroll
    for (int i = 0; i < 2; i++)
#pragma unroll
        for (int j = 0; j < 4; j++) {
#pragma unroll
            for (int e = 0; e < acc[i][j].num_elements; e++)
                acc[i][j].x[e] = fmaxf(acc[i][j].x[e], 0.0f);
            int r = row0 + wr * 32 + i * 16;
            int c = wc * 64 + j * 16;
            wmma::store_matrix_sync(&xout[(size_t)r * HID + c], acc[i][j], HID,
                                    wmma::mem_row_major);
        }
}

// ---------------- global add pool: block per graph (batch is SORTED) --------
__global__ void pool_kernel(const float* __restrict__ x, const int* __restrict__ batch,
                            float* __restrict__ pool) {
    __shared__ int s_beg, s_end;
    int g = blockIdx.x;
    int t = threadIdx.x;
    if (t == 0) {
        int lo = 0, hi = N_NODES;
        while (lo < hi) { int m = (lo + hi) >> 1; if (batch[m] < g) lo = m + 1; else hi = m; }
        s_beg = lo;
    }
    if (t == 1) {
        int lo = 0, hi = N_NODES;
        while (lo < hi) { int m = (lo + hi) >> 1; if (batch[m] < g + 1) lo = m + 1; else hi = m; }
        s_end = lo;
    }
    __syncthreads();
    int beg = s_beg, end = s_end;
    float s = 0.0f;
    for (int n = beg; n < end; n++) s += x[(size_t)n * HID + t];
    pool[(size_t)g * HID + t] = s;
}

// ---------------- MLP head + log_softmax: block per graph ----------------
__global__ void mlp_kernel(const float* __restrict__ pool,
                           const float* __restrict__ W1, const float* __restrict__ b1,
                           const float* __restrict__ W2, const float* __restrict__ b2,
                           float* __restrict__ out) {
    __shared__ float sg[HID];
    __shared__ float sh[HID];
    __shared__ float sl[N_CLASSES];
    int gph = blockIdx.x;
    int t = threadIdx.x;

    sg[t] = fmaxf(pool[(size_t)gph * HID + t], 0.0f);
    __syncthreads();

    float acc = b1[t];
    const float* w1r = W1 + (size_t)t * HID;
#pragma unroll 8
    for (int k = 0; k < HID; k++) acc += sg[k] * w1r[k];
    sh[t] = fmaxf(acc, 0.0f);
    __syncthreads();

    if (t < N_CLASSES) {
        float a = b2[t];
        const float* w2r = W2 + (size_t)t * HID;
#pragma unroll 8
        for (int k = 0; k < HID; k++) a += sh[k] * w2r[k];
        sl[t] = a;
    }
    __syncthreads();

    if (t == 0) {
        float m = -1e30f;
        for (int c = 0; c < N_CLASSES; c++) m = fmaxf(m, sl[c]);
        float s = 0.0f;
        for (int c = 0; c < N_CLASSES; c++) s += expf(sl[c] - m);
        float lse = m + logf(s);
        for (int c = 0; c < N_CLASSES; c++) out[(size_t)gph * N_CLASSES + c] = sl[c] - lse;
    }
}

// ---------------- launch ----------------
extern "C" void kernel_launch(void* const* d_in, const int* in_sizes, int n_in,
                              void* d_out, int out_size) {
    const float* x     = (const float*)d_in[0];
    // d_in[1] = edge_attr (ignored by SAGEConv)
    const int*   ei    = (const int*)d_in[2];
    const int*   srcE  = ei;
    const int*   dstE  = ei + N_EDGES;
    const int*   batch = (const int*)d_in[3];
    const float* Wl    = (const float*)d_in[4];
    const float* bl    = (const float*)d_in[5];
    const float* Wr    = (const float*)d_in[6];
    const float* W1    = (const float*)d_in[7];
    const float* b1    = (const float*)d_in[8];
    const float* W2    = (const float*)d_in[9];
    const float* b2    = (const float*)d_in[10];
    float* out = (float*)d_out;

    int *p_cnt, *p_row, *p_tmp, *p_csr, *p_bsum;
    float *p_mean, *p_h0, *p_h1, *p_pool, *p_btile;
    __nv_bfloat16* p_wblob;
    cudaGetSymbolAddress((void**)&p_cnt, g_cnt);
    cudaGetSymbolAddress((void**)&p_row, g_row);
    cudaGetSymbolAddress((void**)&p_tmp, g_tmp);
    cudaGetSymbolAddress((void**)&p_csr, g_csr);
    cudaGetSymbolAddress((void**)&p_bsum, g_bsum);
    cudaGetSymbolAddress((void**)&p_mean, g_mean);
    cudaGetSymbolAddress((void**)&p_h0, g_h0);
    cudaGetSymbolAddress((void**)&p_h1, g_h1);
    cudaGetSymbolAddress((void**)&p_pool, g_pool);
    cudaGetSymbolAddress((void**)&p_btile, g_btile);
    cudaGetSymbolAddress((void**)&p_wblob, g_Wblob);

    static int smem_set = 0;
    if (!smem_set) {
        cudaFuncSetAttribute(gemm_wmma_kernel,
                             cudaFuncAttributeMaxDynamicSharedMemorySize, GEMM_SMEM);
        smem_set = 1;
    }

    const int TB = 256;
    const int edge_blocks = (N_EDGES + TB - 1) / TB;
    const int warp_node_blocks = (N_NODES * 32 + TB - 1) / TB;
    const int gemm_blocks = (N_NODES + 127) / 128;   // 391

    // CSR build (reused by all 3 layers)
    cudaMemsetAsync(p_cnt, 0, N_NODES * sizeof(int), 0);
    count_kernel<<<edge_blocks, TB>>>(dstE, p_cnt, N_EDGES);
    scan_partial_kernel<<<SCAN_NB, SCAN_B>>>(p_cnt, p_bsum);
    scan_apply_kernel<<<SCAN_NB, SCAN_B>>>(p_cnt, p_bsum, p_row, p_tmp);
    fill_csr_kernel<<<edge_blocks, TB>>>(srcE, dstE, p_tmp, p_csr, N_EDGES);

    // precompute W hi/lo blobs + bias tiles
    prep_w_kernel<<<(N_LAYERS * 2 * 128 * 32 + TB - 1) / TB, TB>>>(Wl, Wr, p_wblob);
    prep_bias_kernel<<<(N_LAYERS * 16 * HID + TB - 1) / TB, TB>>>(bl, p_btile);

    const float* cur = x;
    float* bufs[2] = {p_h0, p_h1};
    for (int l = 0; l < N_LAYERS; l++) {
        aggregate_kernel<<<warp_node_blocks, TB>>>(cur, p_mean);
        gemm_wmma_kernel<<<gemm_blocks, TB, GEMM_SMEM>>>(
            cur, p_mean, p_wblob + (size_t)(l * 2) * 2 * TILE_ELEMS,
            p_btile + l * 16 * HID, bufs[l & 1]);
        cur = bufs[l & 1];
    }

    pool_kernel<<<N_GRAPHS, HID>>>(cur, batch, p_pool);
    mlp_kernel<<<N_GRAPHS, HID>>>(p_pool, W1, b1, W2, b2, out);
}

// round 16
// speedup vs baseline: 1.1452x; 1.0162x over previous
#include <cuda_runtime.h>
#include <cuda_bf16.h>
#include <mma.h>
#include <math.h>
#include <stdint.h>

using namespace nvcuda;

#define N_NODES 50000
#define N_PAD 50048                   // padded for direct wmma stores
#define N_EDGES 600000
#define N_GRAPHS 500
#define HID 128
#define N_LAYERS 3
#define N_CLASSES 10

#define SCAN_B 512
#define SCAN_NB ((N_NODES + SCAN_B - 1) / SCAN_B)   // 98

#define LDA 136                       // bf16 stride (pad 8 halves = 16B)
#define TILE_ELEMS (128 * LDA)        // 17408 bf16 per plane
#define SM_AH 0
#define SM_AL TILE_ELEMS
#define SM_BH (2 * TILE_ELEMS)
#define GEMM_SMEM (3 * TILE_ELEMS * 2)   // 104448 B -> 2 CTAs/SM

// ---------------- scratch (device globals; no allocs allowed) ----------------
__device__ int   g_cnt[N_NODES];
__device__ int   g_row[N_NODES + 1];
__device__ int   g_tmp[N_NODES];
__device__ int   g_csr[N_EDGES];
__device__ int   g_bsum[SCAN_NB];
__device__ float g_mean[(size_t)N_PAD * HID];
__device__ float g_h0[(size_t)N_PAD * HID];
__device__ float g_h1[(size_t)N_PAD * HID];
// W hi/lo blobs in padded-LDA layout: [layer][side][BH ; BL] bf16
__device__ __align__(16) __nv_bfloat16 g_Wblob[(size_t)N_LAYERS * 2 * 2 * TILE_ELEMS];
// bias tiles: [layer][16 rows][128 cols], rows replicated
__device__ __align__(16) float g_btile[N_LAYERS * 16 * HID];

// ---------------- CSR build (vectorized 4 edges/thread) ----------------
__global__ void count_kernel(const int* __restrict__ dst, int* __restrict__ cnt) {
    int i = (blockIdx.x * blockDim.x + threadIdx.x) * 4;
    if (i + 3 < N_EDGES) {
        int4 d = *(const int4*)(dst + i);
        atomicAdd(&cnt[d.x], 1);
        atomicAdd(&cnt[d.y], 1);
        atomicAdd(&cnt[d.z], 1);
        atomicAdd(&cnt[d.w], 1);
    } else {
        for (int e = i; e < N_EDGES; e++) atomicAdd(&cnt[dst[e]], 1);
    }
}

__global__ void scan_partial_kernel(const int* __restrict__ cnt, int* __restrict__ bsum) {
    __shared__ int sh[SCAN_B];
    int t = threadIdx.x;
    int i = blockIdx.x * SCAN_B + t;
    sh[t] = (i < N_NODES) ? cnt[i] : 0;
    __syncthreads();
#pragma unroll
    for (int off = SCAN_B / 2; off > 0; off >>= 1) {
        if (t < off) sh[t] += sh[t + off];
        __syncthreads();
    }
    if (t == 0) bsum[blockIdx.x] = sh[0];
}

// fused: per-block offset from bsum + local scan + row/tmp write
__global__ void scan_apply_kernel(const int* __restrict__ cnt, const int* __restrict__ bsum,
                                  int* __restrict__ row, int* __restrict__ tmp) {
    __shared__ int sh[SCAN_B];
    __shared__ int sb[128];
    __shared__ int s_boff;
    int t = threadIdx.x;
    int i = blockIdx.x * SCAN_B + t;

    if (t < 128) sb[t] = (t < blockIdx.x && t < SCAN_NB) ? bsum[t] : 0;
    __syncthreads();
    if (t < 64) sb[t] += sb[t + 64];
    __syncthreads();
    if (t < 32) {
        int v = sb[t] + sb[t + 32];
#pragma unroll
        for (int off = 16; off > 0; off >>= 1)
            v += __shfl_down_sync(0xFFFFFFFF, v, off);
        if (t == 0) s_boff = v;
    }

    int v = (i < N_NODES) ? cnt[i] : 0;
    sh[t] = v;
    __syncthreads();
#pragma unroll
    for (int off = 1; off < SCAN_B; off <<= 1) {
        int add = (t >= off) ? sh[t - off] : 0;
        __syncthreads();
        sh[t] += add;
        __syncthreads();
    }
    int excl = s_boff + sh[t] - v;
    if (i < N_NODES) { row[i] = excl; tmp[i] = excl; }
    if (i == N_NODES - 1) row[N_NODES] = excl + v;
}

__global__ void fill_csr_kernel(const int* __restrict__ src, const int* __restrict__ dst,
                                int* __restrict__ tmp, int* __restrict__ csr) {
    int i = (blockIdx.x * blockDim.x + threadIdx.x) * 4;
    if (i + 3 < N_EDGES) {
        int4 d = *(const int4*)(dst + i);
        int4 s = *(const int4*)(src + i);
        int p0 = atomicAdd(&tmp[d.x], 1);
        int p1 = atomicAdd(&tmp[d.y], 1);
        int p2 = atomicAdd(&tmp[d.z], 1);
        int p3 = atomicAdd(&tmp[d.w], 1);
        csr[p0] = s.x; csr[p1] = s.y; csr[p2] = s.z; csr[p3] = s.w;
    } else {
        for (int e = i; e < N_EDGES; e++) {
            int p = atomicAdd(&tmp[dst[e]], 1);
            csr[p] = src[e];
        }
    }
}

// ---------------- W prep: fp32 [j][k] -> bf16 hi/lo in padded-LDA layout -----
__global__ void prep_w_kernel(const float* __restrict__ Wl, const float* __restrict__ Wr,
                              __nv_bfloat16* __restrict__ blob) {
    int i = blockIdx.x * blockDim.x + threadIdx.x;   // one float4 per thread
    if (i >= N_LAYERS * 2 * 128 * 32) return;
    int kq   = i & 31;           // k/4
    int j    = (i >> 5) & 127;
    int side = (i >> 12) & 1;
    int l    = i >> 13;
    int k = kq << 2;
    const float* W = side ? Wr : Wl;
    float4 v = *(const float4*)(W + (size_t)l * 16384 + j * HID + k);
    __nv_bfloat162 h0 = __floats2bfloat162_rn(v.x, v.y);
    __nv_bfloat162 h1 = __floats2bfloat162_rn(v.z, v.w);
    float2 f0 = __bfloat1622float2(h0);
    float2 f1 = __bfloat1622float2(h1);
    __nv_bfloat162 l0 = __floats2bfloat162_rn(v.x - f0.x, v.y - f0.y);
    __nv_bfloat162 l1 = __floats2bfloat162_rn(v.z - f1.x, v.w - f1.y);
    __nv_bfloat16* base = blob + ((size_t)(l * 2 + side)) * 2 * TILE_ELEMS;
    *(__nv_bfloat162*)&base[j * LDA + k]                  = h0;
    *(__nv_bfloat162*)&base[j * LDA + k + 2]              = h1;
    *(__nv_bfloat162*)&base[TILE_ELEMS + j * LDA + k]     = l0;
    *(__nv_bfloat162*)&base[TILE_ELEMS + j * LDA + k + 2] = l1;
}

// bias tiles: replicate bias row 16x per layer
__global__ void prep_bias_kernel(const float* __restrict__ bl, float* __restrict__ btile) {
    int i = blockIdx.x * blockDim.x + threadIdx.x;
    if (i >= N_LAYERS * 16 * HID) return;
    int c = i & 127;
    int l = i >> 11;
    btile[i] = bl[l * HID + c];
}

// ---------------- mean aggregation: warp per node, CSR gather ----------------
__global__ void aggregate_kernel(const float* __restrict__ x, float* __restrict__ mean) {
    int w = (blockIdx.x * blockDim.x + threadIdx.x) >> 5;
    int lane = threadIdx.x & 31;
    if (w >= N_NODES) return;
    int beg = g_row[w];
    int end = g_row[w + 1];
    float4 s = make_float4(0.f, 0.f, 0.f, 0.f);
    for (int i = beg; i < end; i++) {
        int sn = g_csr[i];
        float4 v = *(const float4*)(x + (size_t)sn * HID + lane * 4);
        s.x += v.x; s.y += v.y; s.z += v.z; s.w += v.w;
    }
    float ic = 1.0f / fmaxf((float)(end - beg), 1.0f);
    s.x *= ic; s.y *= ic; s.z *= ic; s.w *= ic;
    *(float4*)(mean + (size_t)w * HID + lane * 4) = s;
}

// ---------------- wmma (HMMA) fused dual GEMM, bf16x3 emulation -------------
__global__ __launch_bounds__(256, 2) void gemm_wmma_kernel(
    const float* __restrict__ xin, const float* __restrict__ mean,
    const __nv_bfloat16* __restrict__ Wblob,   // layer base: [side][BH;BL]
    const float* __restrict__ btile,           // [16][128] replicated bias
    float* __restrict__ xout)                  // padded to N_PAD rows
{
    extern __shared__ __nv_bfloat16 sm[];
    const int tid = threadIdx.x;
    const int wid = tid >> 5;
    const int wr = wid >> 1;            // warp row group (0..3)
    const int wc = wid & 1;             // warp col group (0..1)
    const int row0 = blockIdx.x * 128;

    // init accumulators with bias (rows of btile are identical)
    wmma::fragment<wmma::accumulator, 16, 16, 16, float> acc[2][4];
#pragma unroll
    for (int i = 0; i < 2; i++)
#pragma unroll
        for (int j = 0; j < 4; j++)
            wmma::load_matrix_sync(acc[i][j], btile + wc * 64 + j * 16, HID,
                                   wmma::mem_row_major);

    for (int side = 0; side < 2; side++) {
        const float* A = side ? xin : mean;
        const __nv_bfloat16* BH = Wblob + (size_t)side * 2 * TILE_ELEMS;
        const __nv_bfloat16* BL = BH + TILE_ELEMS;
        __syncthreads();   // previous side's smem fully consumed

        // stage BH plane: straight uint4 copy (34816 B)
        {
            const uint4* wsrc = (const uint4*)BH;
            uint4* wdst = (uint4*)(sm + SM_BH);
            for (int i = tid; i < 2176; i += 256) wdst[i] = wsrc[i];
        }
        // stage A: 128 rows x 128 cols fp32 -> bf16 hi/lo
        for (int i = tid; i < 128 * 32; i += 256) {
            int r = i >> 5;
            int c = (i & 31) << 2;
            int gr = row0 + r;
            float4 v = make_float4(0.f, 0.f, 0.f, 0.f);
            if (gr < N_NODES) v = *(const float4*)(A + (size_t)gr * HID + c);
            __nv_bfloat162 h0 = __floats2bfloat162_rn(v.x, v.y);
            __nv_bfloat162 h1 = __floats2bfloat162_rn(v.z, v.w);
            float2 f0 = __bfloat1622float2(h0);
            float2 f1 = __bfloat1622float2(h1);
            __nv_bfloat162 l0 = __floats2bfloat162_rn(v.x - f0.x, v.y - f0.y);
            __nv_bfloat162 l1 = __floats2bfloat162_rn(v.z - f1.x, v.w - f1.y);
            int o = r * LDA + c;
            *(__nv_bfloat162*)&sm[SM_AH + o]     = h0;
            *(__nv_bfloat162*)&sm[SM_AH + o + 2] = h1;
            *(__nv_bfloat162*)&sm[SM_AL + o]     = l0;
            *(__nv_bfloat162*)&sm[SM_AL + o + 2] = l1;
        }
        __syncthreads();

#pragma unroll
        for (int k = 0; k < HID; k += 16) {
            wmma::fragment<wmma::matrix_a, 16, 16, 16, __nv_bfloat16, wmma::row_major> ah[2], al[2];
            wmma::fragment<wmma::matrix_b, 16, 16, 16, __nv_bfloat16, wmma::col_major> bh[4], bl[4];
#pragma unroll
            for (int i = 0; i < 2; i++) {
                int r = wr * 32 + i * 16;
                wmma::load_matrix_sync(ah[i], &sm[SM_AH + r * LDA + k], LDA);
                wmma::load_matrix_sync(al[i], &sm[SM_AL + r * LDA + k], LDA);
            }
#pragma unroll
            for (int j = 0; j < 4; j++) {
                int cj = wc * 64 + j * 16;
                wmma::load_matrix_sync(bh[j], &sm[SM_BH + cj * LDA + k], LDA);  // smem
                wmma::load_matrix_sync(bl[j], &BL[cj * LDA + k], LDA);          // global (L1)
            }
#pragma unroll
            for (int i = 0; i < 2; i++)
#pragma unroll
                for (int j = 0; j < 4; j++) {
                    wmma::mma_sync(acc[i][j], ah[i], bh[j], acc[i][j]);
                    wmma::mma_sync(acc[i][j], ah[i], bl[j], acc[i][j]);
                    wmma::mma_sync(acc[i][j], al[i], bh[j], acc[i][j]);
                }
        }
    }

    // epilogue: relu on fragments, direct global store (padded buffer)
#pragma unroll
    for (int i = 0; i < 2; i++)
#pragma unroll
        for (int j = 0; j < 4; j++) {
#pragma unroll
            for (int e = 0; e < acc[i][j].num_elements; e++)
                acc[i][j].x[e] = fmaxf(acc[i][j].x[e], 0.0f);
            int r = row0 + wr * 32 + i * 16;
            int c = wc * 64 + j * 16;
            wmma::store_matrix_sync(&xout[(size_t)r * HID + c], acc[i][j], HID,
                                    wmma::mem_row_major);
        }
}

// ---------------- fused pool + MLP + log_softmax: block per graph -----------
__global__ void pool_mlp_kernel(const float* __restrict__ x, const int* __restrict__ batch,
                                const float* __restrict__ W1, const float* __restrict__ b1,
                                const float* __restrict__ W2, const float* __restrict__ b2,
                                float* __restrict__ out) {
    __shared__ int s_beg, s_end;
    __shared__ float sg[HID];
    __shared__ float sh[HID];
    __shared__ float sl[N_CLASSES];
    int g = blockIdx.x;
    int t = threadIdx.x;
    if (t == 0) {
        int lo = 0, hi = N_NODES;
        while (lo < hi) { int m = (lo + hi) >> 1; if (batch[m] < g) lo = m + 1; else hi = m; }
        s_beg = lo;
    }
    if (t == 1) {
        int lo = 0, hi = N_NODES;
        while (lo < hi) { int m = (lo + hi) >> 1; if (batch[m] < g + 1) lo = m + 1; else hi = m; }
        s_end = lo;
    }
    __syncthreads();
    int beg = s_beg, end = s_end;
    float s = 0.0f;
    for (int n = beg; n < end; n++) s += x[(size_t)n * HID + t];
    sg[t] = fmaxf(s, 0.0f);   // relu(global_add_pool)
    __syncthreads();

    float acc = b1[t];
    const float* w1r = W1 + (size_t)t * HID;
#pragma unroll 8
    for (int k = 0; k < HID; k++) acc += sg[k] * w1r[k];
    sh[t] = fmaxf(acc, 0.0f);
    __syncthreads();

    if (t < N_CLASSES) {
        float a = b2[t];
        const float* w2r = W2 + (size_t)t * HID;
#pragma unroll 8
        for (int k = 0; k < HID; k++) a += sh[k] * w2r[k];
        sl[t] = a;
    }
    __syncthreads();

    if (t == 0) {
        float m = -1e30f;
        for (int c = 0; c < N_CLASSES; c++) m = fmaxf(m, sl[c]);
        float su = 0.0f;
        for (int c = 0; c < N_CLASSES; c++) su += expf(sl[c] - m);
        float lse = m + logf(su);
        for (int c = 0; c < N_CLASSES; c++) out[(size_t)g * N_CLASSES + c] = sl[c] - lse;
    }
}

// ---------------- launch ----------------
extern "C" void kernel_launch(void* const* d_in, const int* in_sizes, int n_in,
                              void* d_out, int out_size) {
    const float* x     = (const float*)d_in[0];
    // d_in[1] = edge_attr (ignored by SAGEConv)
    const int*   ei    = (const int*)d_in[2];
    const int*   srcE  = ei;
    const int*   dstE  = ei + N_EDGES;
    const int*   batch = (const int*)d_in[3];
    const float* Wl    = (const float*)d_in[4];
    const float* bl    = (const float*)d_in[5];
    const float* Wr    = (const float*)d_in[6];
    const float* W1    = (const float*)d_in[7];
    const float* b1    = (const float*)d_in[8];
    const float* W2    = (const float*)d_in[9];
    const float* b2    = (const float*)d_in[10];
    float* out = (float*)d_out;

    int *p_cnt, *p_row, *p_tmp, *p_csr, *p_bsum;
    float *p_mean, *p_h0, *p_h1, *p_btile;
    __nv_bfloat16* p_wblob;
    cudaGetSymbolAddress((void**)&p_cnt, g_cnt);
    cudaGetSymbolAddress((void**)&p_row, g_row);
    cudaGetSymbolAddress((void**)&p_tmp, g_tmp);
    cudaGetSymbolAddress((void**)&p_csr, g_csr);
    cudaGetSymbolAddress((void**)&p_bsum, g_bsum);
    cudaGetSymbolAddress((void**)&p_mean, g_mean);
    cudaGetSymbolAddress((void**)&p_h0, g_h0);
    cudaGetSymbolAddress((void**)&p_h1, g_h1);
    cudaGetSymbolAddress((void**)&p_btile, g_btile);
    cudaGetSymbolAddress((void**)&p_wblob, g_Wblob);

    static int smem_set = 0;
    if (!smem_set) {
        cudaFuncSetAttribute(gemm_wmma_kernel,
                             cudaFuncAttributeMaxDynamicSharedMemorySize, GEMM_SMEM);
        smem_set = 1;
    }

    const int TB = 256;
    const int edge4_blocks = (N_EDGES / 4 + TB - 1) / TB;
    const int warp_node_blocks = (N_NODES * 32 + TB - 1) / TB;
    const int gemm_blocks = (N_NODES + 127) / 128;   // 391

    // CSR build (reused by all 3 layers)
    cudaMemsetAsync(p_cnt, 0, N_NODES * sizeof(int), 0);
    count_kernel<<<edge4_blocks, TB>>>(dstE, p_cnt);
    scan_partial_kernel<<<SCAN_NB, SCAN_B>>>(p_cnt, p_bsum);
    scan_apply_kernel<<<SCAN_NB, SCAN_B>>>(p_cnt, p_bsum, p_row, p_tmp);
    fill_csr_kernel<<<edge4_blocks, TB>>>(srcE, dstE, p_tmp, p_csr);

    // precompute W hi/lo blobs + bias tiles
    prep_w_kernel<<<(N_LAYERS * 2 * 128 * 32 + TB - 1) / TB, TB>>>(Wl, Wr, p_wblob);
    prep_bias_kernel<<<(N_LAYERS * 16 * HID + TB - 1) / TB, TB>>>(bl, p_btile);

    const float* cur = x;
    float* bufs[2] = {p_h0, p_h1};
    for (int l = 0; l < N_LAYERS; l++) {
        aggregate_kernel<<<warp_node_blocks, TB>>>(cur, p_mean);
        gemm_wmma_kernel<<<gemm_blocks, TB, GEMM_SMEM>>>(
            cur, p_mean, p_wblob + (size_t)(l * 2) * 2 * TILE_ELEMS,
            p_btile + l * 16 * HID, bufs[l & 1]);
        cur = bufs[l & 1];
    }

    pool_mlp_kernel<<<N_GRAPHS, HID>>>(cur, batch, W1, b1, W2, b2, out);
}